// round 3
// baseline (speedup 1.0000x reference)
#include <cuda_runtime.h>

// PositionalEncoding: out[b,t,i] = x[b,t,i] + P[t,i]
//   P[2f,   i] = sin(f / 10000^(2i/F))
//   P[2f+1, i] = cos(f / 10000^(2i/F))
// x: [32, 2048, 1024] fp32. HBM-streaming-bound (512MB floor).
// R3: one CTA per row (full 32-batch amortization of sin/cos), 256-bit
// global loads/stores (LDG.E.256 / STG.E.256 on sm_103a) with streaming
// (.cs) cache policy. 128 threads x 8 floats = 1024 cols per row.

#define PE_T 2048
#define PE_F 1024
#define PE_B 32

__device__ __forceinline__ void ldg256_cs(const float* p, float v[8]) {
    asm volatile("ld.global.cs.v8.f32 {%0,%1,%2,%3,%4,%5,%6,%7}, [%8];"
                 : "=f"(v[0]), "=f"(v[1]), "=f"(v[2]), "=f"(v[3]),
                   "=f"(v[4]), "=f"(v[5]), "=f"(v[6]), "=f"(v[7])
                 : "l"(p));
}

__device__ __forceinline__ void stg256_cs(float* p, const float v[8]) {
    asm volatile("st.global.cs.v8.f32 [%0], {%1,%2,%3,%4,%5,%6,%7,%8};"
                 :: "l"(p),
                    "f"(v[0]), "f"(v[1]), "f"(v[2]), "f"(v[3]),
                    "f"(v[4]), "f"(v[5]), "f"(v[6]), "f"(v[7])
                 : "memory");
}

__global__ __launch_bounds__(128)
void pe_add_kernel(const float* __restrict__ x, float* __restrict__ out) {
    const int t = blockIdx.x;            // row 0..2047
    const int c = threadIdx.x;           // 8-float column group 0..127
    const float f = (float)(t >> 1);
    const bool is_sin = (t & 1) == 0;

    float p[8];
#pragma unroll
    for (int k = 0; k < 8; k++) {
        const int i = c * 8 + k;
        const float e = (float)i * (1.0f / 512.0f);   // 2*i/F, exact in fp32
        const float den = powf(10000.0f, e);
        const float ang = f / den;
        p[k] = is_sin ? sinf(ang) : cosf(ang);
    }

    const size_t row_stride = (size_t)PE_T * PE_F;    // floats per batch slice
    const size_t base = (size_t)t * PE_F + (size_t)c * 8;

#pragma unroll 4
    for (int b = 0; b < PE_B; b++) {
        const size_t idx = base + (size_t)b * row_stride;
        float v[8];
        ldg256_cs(x + idx, v);
#pragma unroll
        for (int k = 0; k < 8; k++) v[k] += p[k];
        stg256_cs(out + idx, v);
    }
}

extern "C" void kernel_launch(void* const* d_in, const int* in_sizes, int n_in,
                              void* d_out, int out_size) {
    const float* x = (const float*)d_in[0];
    float* out = (float*)d_out;
    pe_add_kernel<<<PE_T, 128>>>(x, out);
}

// round 5
// speedup vs baseline: 1.0010x; 1.0010x over previous
#include <cuda_runtime.h>

// PositionalEncoding: out[b,t,i] = x[b,t,i] + P[t,i]
//   P[2f,   i] = sin(f / 10000^(2i/F))
//   P[2f+1, i] = cos(f / 10000^(2i/F))
// x: [32, 2048, 1024] fp32. HBM-streaming-bound (512MB floor).
// R4 = R1 champion shape (256 thr x float4, one CTA per row, 32-batch loop)
// with: no occupancy cap, L1-bypass loads (.cg), unroll 16 for deeper MLP.

#define PE_T 2048
#define PE_F 1024
#define PE_B 32

__global__ __launch_bounds__(256)
void pe_add_kernel(const float* __restrict__ x, float* __restrict__ out) {
    const int t = blockIdx.x;          // row 0..2047
    const int c = threadIdx.x;         // float4 column 0..255
    const float f = (float)(t >> 1);
    const bool is_sin = (t & 1) == 0;

    float pv[4];
#pragma unroll
    for (int k = 0; k < 4; k++) {
        const int i = c * 4 + k;
        const float e = (float)i * (1.0f / 512.0f);   // 2*i/F, exact in fp32
        const float den = powf(10000.0f, e);
        const float ang = f / den;
        pv[k] = is_sin ? sinf(ang) : cosf(ang);
    }
    const float4 p = make_float4(pv[0], pv[1], pv[2], pv[3]);

    const float4* __restrict__ x4 = (const float4*)x;
    float4* __restrict__ o4 = (float4*)out;
    const size_t row_stride4 = (size_t)PE_T * (PE_F / 4);   // float4 per batch slice
    const size_t base = (size_t)t * (PE_F / 4) + (size_t)c;

#pragma unroll 16
    for (int b = 0; b < PE_B; b++) {
        const size_t idx = base + (size_t)b * row_stride4;
        float4 v = __ldcg(&x4[idx]);      // L2-only: stream is touched once
        v.x += p.x;
        v.y += p.y;
        v.z += p.z;
        v.w += p.w;
        o4[idx] = v;
    }
}

extern "C" void kernel_launch(void* const* d_in, const int* in_sizes, int n_in,
                              void* d_out, int out_size) {
    const float* x = (const float*)d_in[0];
    float* out = (float*)d_out;
    pe_add_kernel<<<PE_T, 256>>>(x, out);
}